// round 1
// baseline (speedup 1.0000x reference)
#include <cuda_runtime.h>
#include <cuda_bf16.h>
#include <math_constants.h>

// Problem constants
#define BATCH 4
#define CDIM 256
#define NTOK 4096          // 64*64
#define HEADS 4
#define DH 32
#define HID 128            // HEADS*DH
#define OQKV 384           // 3*HID
#define NPB 1048576        // CDIM*NTOK per batch
#define SCALE_LOG2E 0.25494291280534f  // 32^-0.5 * log2(e)

// ---------------- device scratch (no mallocs allowed) ----------------
__device__ float g_psum[BATCH * 64];
__device__ float g_psq [BATCH * 64];
__device__ float g_mu[BATCH];
__device__ float g_rs[BATCH];
__device__ float g_wt_qkv[CDIM * OQKV];   // [c][o]
__device__ float g_wt_out[HID * CDIM];    // [c][o]
__device__ float g_q[BATCH * HEADS * NTOK * DH];  // [bh][i][d], pre-scaled
__device__ float g_k[BATCH * HEADS * NTOK * DH];
__device__ float g_v[BATCH * HEADS * NTOK * DH];
__device__ float g_ao[BATCH * HID * NTOK];        // [b][c][i]

__device__ __forceinline__ float ex2(float x) {
    float y;
    asm("ex2.approx.ftz.f32 %0, %1;" : "=f"(y) : "f"(x));
    return y;
}

// ---------------- kernel 0: transpose weights ----------------
__global__ void k_transpose(const float* __restrict__ wqkv,
                            const float* __restrict__ wout) {
    int idx = blockIdx.x * 256 + threadIdx.x;
    if (idx < OQKV * CDIM) {
        int o = idx / CDIM, c = idx % CDIM;
        g_wt_qkv[c * OQKV + o] = wqkv[idx];
    }
    if (idx < CDIM * HID) {
        int o = idx / HID, c = idx % HID;
        g_wt_out[c * CDIM + o] = wout[idx];
    }
}

// ---------------- kernel 1: per-batch sum / sumsq partials ----------------
__global__ void k_reduce1(const float* __restrict__ x) {
    int b = blockIdx.y;
    int blk = blockIdx.x;            // 64 blocks per batch
    int tid = threadIdx.x;           // 256 threads
    const float4* xb = (const float4*)(x + (size_t)b * NPB);
    float s = 0.f, sq = 0.f;
    int base = blk * 4096 + tid;
    #pragma unroll
    for (int t = 0; t < 16; t++) {
        float4 v = xb[base + t * 256];
        s  += (v.x + v.y) + (v.z + v.w);
        sq += (v.x * v.x + v.y * v.y) + (v.z * v.z + v.w * v.w);
    }
    __shared__ float ss[256], sg[256];
    ss[tid] = s; sg[tid] = sq;
    __syncthreads();
    for (int off = 128; off >= 1; off >>= 1) {
        if (tid < off) { ss[tid] += ss[tid + off]; sg[tid] += sg[tid + off]; }
        __syncthreads();
    }
    if (tid == 0) { g_psum[b * 64 + blk] = ss[0]; g_psq[b * 64 + blk] = sg[0]; }
}

// ---------------- kernel 2: finalize mean / rsigma ----------------
__global__ void k_reduce2() {
    int tid = threadIdx.x;   // 256
    int b = tid / 64, j = tid % 64;
    __shared__ float ss[256], sg[256];
    ss[tid] = g_psum[tid]; sg[tid] = g_psq[tid];
    __syncthreads();
    for (int off = 32; off >= 1; off >>= 1) {
        if (j < off) { ss[tid] += ss[tid + off]; sg[tid] += sg[tid + off]; }
        __syncthreads();
    }
    if (j == 0) {
        float mu = ss[tid] * (1.f / (float)NPB);
        float var = sg[tid] * (1.f / (float)NPB) - mu * mu;
        g_mu[b] = mu;
        g_rs[b] = rsqrtf(var + 1e-5f);
    }
}

// ---------------- kernel 3: normalize + QKV GEMM ----------------
// qkv[b][o][i] = sum_c wT[c][o] * xn[b][c][i]; scatter into g_q/g_k/g_v
__global__ void __launch_bounds__(256) k_qkv(const float* __restrict__ x,
                                             const float* __restrict__ gamma,
                                             const float* __restrict__ beta) {
    int b  = blockIdx.z;
    int i0 = blockIdx.x * 64;
    int o0 = blockIdx.y * 64;
    float mu = g_mu[b], rs = g_rs[b];
    __shared__ float xs[16][68];
    __shared__ float ws[16][68];
    int tid = threadIdx.x;
    int tx = tid & 15, ty = tid >> 4;
    int lrow = tid >> 4, lcol = (tid & 15) * 4;
    const float* xb = x + (size_t)b * NPB;
    float acc[4][4] = {};
    for (int k0 = 0; k0 < CDIM; k0 += 16) {
        int c = k0 + lrow;
        float a = rs * gamma[c];
        float bb = beta[c] - mu * a;
        float4 xv = *(const float4*)(xb + (size_t)c * NTOK + i0 + lcol);
        xs[lrow][lcol + 0] = xv.x * a + bb;
        xs[lrow][lcol + 1] = xv.y * a + bb;
        xs[lrow][lcol + 2] = xv.z * a + bb;
        xs[lrow][lcol + 3] = xv.w * a + bb;
        float4 wv = *(const float4*)(g_wt_qkv + c * OQKV + o0 + lcol);
        ws[lrow][lcol + 0] = wv.x;
        ws[lrow][lcol + 1] = wv.y;
        ws[lrow][lcol + 2] = wv.z;
        ws[lrow][lcol + 3] = wv.w;
        __syncthreads();
        #pragma unroll
        for (int kk = 0; kk < 16; kk++) {
            float av[4], bv[4];
            #pragma unroll
            for (int u = 0; u < 4; u++) av[u] = xs[kk][tx * 4 + u];
            #pragma unroll
            for (int u = 0; u < 4; u++) bv[u] = ws[kk][ty * 4 + u];
            #pragma unroll
            for (int oi = 0; oi < 4; oi++)
                #pragma unroll
                for (int ii = 0; ii < 4; ii++)
                    acc[oi][ii] = fmaf(bv[oi], av[ii], acc[oi][ii]);
        }
        __syncthreads();
    }
    #pragma unroll
    for (int oi = 0; oi < 4; oi++) {
        int o = o0 + ty * 4 + oi;
        int which = o >> 7;
        int head = (o & 127) >> 5;
        int d = o & 31;
        size_t base = ((size_t)(b * HEADS + head) * NTOK) * DH + d;
        #pragma unroll
        for (int ii = 0; ii < 4; ii++) {
            int i = i0 + tx * 4 + ii;
            float val = acc[oi][ii];
            size_t idx = base + (size_t)i * DH;
            if (which == 0)      g_q[idx] = val * SCALE_LOG2E;
            else if (which == 1) g_k[idx] = val;
            else                 g_v[idx] = val;
        }
    }
}

// ---------------- kernel 4: flash attention (fp32 scalar) ----------------
// grid: (32 q-tiles, 16 bh). 128 threads, 1 query row per thread.
__global__ void __launch_bounds__(128) k_attn() {
    int tid = threadIdx.x;
    int bh = blockIdx.y;
    int i0 = blockIdx.x * 128;
    int i = i0 + tid;

    __shared__ float4 ks4[64 * 8];
    __shared__ float4 vs4[64 * 8];

    const float4* qp = (const float4*)(g_q + ((size_t)bh * NTOK + i) * DH);
    const float4* kbase = (const float4*)(g_k + (size_t)bh * NTOK * DH);
    const float4* vbase = (const float4*)(g_v + (size_t)bh * NTOK * DH);

    float4 qv[8], ov[8];
    #pragma unroll
    for (int w = 0; w < 8; w++) { qv[w] = qp[w]; ov[w] = make_float4(0.f, 0.f, 0.f, 0.f); }
    float m = -CUDART_INF_F, l = 0.f;

    for (int j0 = 0; j0 < NTOK; j0 += 64) {
        const float4* kt = kbase + j0 * 8;
        const float4* vt = vbase + j0 * 8;
        #pragma unroll
        for (int t = 0; t < 4; t++) {
            ks4[t * 128 + tid] = kt[t * 128 + tid];
            vs4[t * 128 + tid] = vt[t * 128 + tid];
        }
        __syncthreads();

        for (int c0 = 0; c0 < 64; c0 += 16) {
            float sv[16];
            float mc = -CUDART_INF_F;
            #pragma unroll
            for (int jj = 0; jj < 16; jj++) {
                int j = c0 + jj;
                float s0 = 0.f, s1 = 0.f, s2 = 0.f, s3 = 0.f;
                #pragma unroll
                for (int w = 0; w < 8; w++) {
                    float4 kk = ks4[j * 8 + w];
                    s0 = fmaf(qv[w].x, kk.x, s0);
                    s1 = fmaf(qv[w].y, kk.y, s1);
                    s2 = fmaf(qv[w].z, kk.z, s2);
                    s3 = fmaf(qv[w].w, kk.w, s3);
                }
                float s = (s0 + s1) + (s2 + s3);
                sv[jj] = s;
                mc = fmaxf(mc, s);
            }
            float mnew = fmaxf(m, mc);
            float corr = ex2(m - mnew);
            l *= corr;
            #pragma unroll
            for (int w = 0; w < 8; w++) {
                ov[w].x *= corr; ov[w].y *= corr; ov[w].z *= corr; ov[w].w *= corr;
            }
            m = mnew;
            #pragma unroll
            for (int jj = 0; jj < 16; jj++) {
                float p = ex2(sv[jj] - m);
                l += p;
                int j = c0 + jj;
                #pragma unroll
                for (int w = 0; w < 8; w++) {
                    float4 vv = vs4[j * 8 + w];
                    ov[w].x = fmaf(p, vv.x, ov[w].x);
                    ov[w].y = fmaf(p, vv.y, ov[w].y);
                    ov[w].z = fmaf(p, vv.z, ov[w].z);
                    ov[w].w = fmaf(p, vv.w, ov[w].w);
                }
            }
        }
        __syncthreads();
    }

    float inv = 1.f / l;
    int b = bh >> 2, h = bh & 3;
    float* dst = g_ao + ((size_t)b * HID + h * DH) * NTOK + i;
    #pragma unroll
    for (int w = 0; w < 8; w++) {
        dst[(w * 4 + 0) * NTOK] = ov[w].x * inv;
        dst[(w * 4 + 1) * NTOK] = ov[w].y * inv;
        dst[(w * 4 + 2) * NTOK] = ov[w].z * inv;
        dst[(w * 4 + 3) * NTOK] = ov[w].w * inv;
    }
}

// ---------------- kernel 5: output GEMM + bias ----------------
// y[b][o][i] = sum_c wT_out[c][o] * ao[b][c][i] + b_out[o]
__global__ void __launch_bounds__(256) k_out(float* __restrict__ y,
                                             const float* __restrict__ b_out) {
    int b  = blockIdx.z;
    int i0 = blockIdx.x * 64;
    int o0 = blockIdx.y * 64;
    __shared__ float xs[16][68];
    __shared__ float ws[16][68];
    int tid = threadIdx.x;
    int tx = tid & 15, ty = tid >> 4;
    int lrow = tid >> 4, lcol = (tid & 15) * 4;
    const float* ab = g_ao + (size_t)b * HID * NTOK;
    float acc[4][4] = {};
    for (int k0 = 0; k0 < HID; k0 += 16) {
        int c = k0 + lrow;
        float4 xv = *(const float4*)(ab + (size_t)c * NTOK + i0 + lcol);
        xs[lrow][lcol + 0] = xv.x;
        xs[lrow][lcol + 1] = xv.y;
        xs[lrow][lcol + 2] = xv.z;
        xs[lrow][lcol + 3] = xv.w;
        float4 wv = *(const float4*)(g_wt_out + c * CDIM + o0 + lcol);
        ws[lrow][lcol + 0] = wv.x;
        ws[lrow][lcol + 1] = wv.y;
        ws[lrow][lcol + 2] = wv.z;
        ws[lrow][lcol + 3] = wv.w;
        __syncthreads();
        #pragma unroll
        for (int kk = 0; kk < 16; kk++) {
            float av[4], bv[4];
            #pragma unroll
            for (int u = 0; u < 4; u++) av[u] = xs[kk][tx * 4 + u];
            #pragma unroll
            for (int u = 0; u < 4; u++) bv[u] = ws[kk][ty * 4 + u];
            #pragma unroll
            for (int oi = 0; oi < 4; oi++)
                #pragma unroll
                for (int ii = 0; ii < 4; ii++)
                    acc[oi][ii] = fmaf(bv[oi], av[ii], acc[oi][ii]);
        }
        __syncthreads();
    }
    #pragma unroll
    for (int oi = 0; oi < 4; oi++) {
        int o = o0 + ty * 4 + oi;
        float bias = b_out[o];
        #pragma unroll
        for (int ii = 0; ii < 4; ii++) {
            int i = i0 + tx * 4 + ii;
            y[((size_t)b * CDIM + o) * NTOK + i] = acc[oi][ii] + bias;
        }
    }
}

// ---------------- launch ----------------
extern "C" void kernel_launch(void* const* d_in, const int* in_sizes, int n_in,
                              void* d_out, int out_size) {
    const float* x     = (const float*)d_in[0];
    const float* gamma = (const float*)d_in[1];
    const float* beta  = (const float*)d_in[2];
    const float* w_qkv = (const float*)d_in[3];
    const float* w_out = (const float*)d_in[4];
    const float* b_out = (const float*)d_in[5];
    float* y = (float*)d_out;

    k_transpose<<<384, 256>>>(w_qkv, w_out);
    k_reduce1<<<dim3(64, BATCH), 256>>>(x);
    k_reduce2<<<1, 256>>>();
    k_qkv<<<dim3(NTOK / 64, OQKV / 64, BATCH), 256>>>(x, gamma, beta);
    k_attn<<<dim3(NTOK / 128, BATCH * HEADS), 128>>>();
    k_out<<<dim3(NTOK / 64, CDIM / 64, BATCH), 256>>>(y, b_out);
}

// round 4
// speedup vs baseline: 3.9488x; 3.9488x over previous
#include <cuda_runtime.h>
#include <cuda_bf16.h>
#include <math_constants.h>
#include <cstdint>

// Problem constants
#define BATCH 4
#define CDIM 256
#define NTOK 4096          // 64*64
#define HEADS 4
#define DH 32
#define HID 128            // HEADS*DH
#define OQKV 384           // 3*HID
#define NPB 1048576        // CDIM*NTOK per batch
#define SCALE_LOG2E 0.25494291280534f  // 32^-0.5 * log2(e)

// ---------------- device scratch ----------------
__device__ float g_psum[BATCH * 64];
__device__ float g_psq [BATCH * 64];
__device__ float g_mu[BATCH];
__device__ float g_rs[BATCH];
__device__ float g_wt_qkv[CDIM * OQKV];   // [c][o]
__device__ float g_wt_out[HID * CDIM];    // [c][o]
__device__ float g_qf[BATCH * HEADS * NTOK * DH];          // [bh][i][d], tf32-rounded, pre-scaled
__device__ float g_kf[BATCH * HEADS * NTOK * DH];          // [bh][j][d], tf32-rounded
__device__ __nv_bfloat16 g_vb[BATCH * HEADS * NTOK * DH];  // [bh][j][d]
__device__ float g_ao[BATCH * HID * NTOK];                 // [b][c][i]

__device__ __forceinline__ float ex2(float x) {
    float y;
    asm("ex2.approx.ftz.f32 %0, %1;" : "=f"(y) : "f"(x));
    return y;
}
__device__ __forceinline__ float tf32r(float x) {
    uint32_t u;
    asm("cvt.rna.tf32.f32 %0, %1;" : "=r"(u) : "f"(x));
    return __uint_as_float(u);
}
__device__ __forceinline__ uint32_t smem_u32(const void* p) {
    uint32_t a;
    asm("{ .reg .u64 t; cvta.to.shared.u64 t, %1; cvt.u32.u64 %0, t; }" : "=r"(a) : "l"(p));
    return a;
}
__device__ __forceinline__ void ldsm_x4_t(uint32_t* r, uint32_t a) {
    asm volatile("ldmatrix.sync.aligned.m8n8.x4.trans.shared.b16 {%0,%1,%2,%3}, [%4];"
                 : "=r"(r[0]), "=r"(r[1]), "=r"(r[2]), "=r"(r[3]) : "r"(a));
}
#define MMA_BF16(d, a, b0_, b1_) \
    asm volatile("mma.sync.aligned.m16n8k16.row.col.f32.bf16.bf16.f32 " \
                 "{%0,%1,%2,%3}, {%4,%5,%6,%7}, {%8,%9}, {%0,%1,%2,%3};" \
                 : "+f"((d)[0]), "+f"((d)[1]), "+f"((d)[2]), "+f"((d)[3]) \
                 : "r"((a)[0]), "r"((a)[1]), "r"((a)[2]), "r"((a)[3]), "r"(b0_), "r"(b1_))
#define MMA_TF32(d, a, b0_, b1_) \
    asm volatile("mma.sync.aligned.m16n8k8.row.col.f32.tf32.tf32.f32 " \
                 "{%0,%1,%2,%3}, {%4,%5,%6,%7}, {%8,%9}, {%0,%1,%2,%3};" \
                 : "+f"((d)[0]), "+f"((d)[1]), "+f"((d)[2]), "+f"((d)[3]) \
                 : "r"((a)[0]), "r"((a)[1]), "r"((a)[2]), "r"((a)[3]), "r"(b0_), "r"(b1_))
#define PACK_BF16X2(r, lo, hi) \
    asm("cvt.rn.bf16x2.f32 %0, %1, %2;" : "=r"(r) : "f"(hi), "f"(lo))

// ---------------- kernel 0: transpose weights ----------------
__global__ void k_transpose(const float* __restrict__ wqkv,
                            const float* __restrict__ wout) {
    int idx = blockIdx.x * 256 + threadIdx.x;
    if (idx < OQKV * CDIM) {
        int o = idx / CDIM, c = idx % CDIM;
        g_wt_qkv[c * OQKV + o] = wqkv[idx];
    }
    if (idx < CDIM * HID) {
        int o = idx / HID, c = idx % HID;
        g_wt_out[c * CDIM + o] = wout[idx];
    }
}

// ---------------- kernel 1: per-batch sum / sumsq partials ----------------
__global__ void k_reduce1(const float* __restrict__ x) {
    int b = blockIdx.y;
    int blk = blockIdx.x;
    int tid = threadIdx.x;
    const float4* xb = (const float4*)(x + (size_t)b * NPB);
    float s = 0.f, sq = 0.f;
    int base = blk * 4096 + tid;
    #pragma unroll
    for (int t = 0; t < 16; t++) {
        float4 v = xb[base + t * 256];
        s  += (v.x + v.y) + (v.z + v.w);
        sq += (v.x * v.x + v.y * v.y) + (v.z * v.z + v.w * v.w);
    }
    __shared__ float ss[256], sg[256];
    ss[tid] = s; sg[tid] = sq;
    __syncthreads();
    for (int off = 128; off >= 1; off >>= 1) {
        if (tid < off) { ss[tid] += ss[tid + off]; sg[tid] += sg[tid + off]; }
        __syncthreads();
    }
    if (tid == 0) { g_psum[b * 64 + blk] = ss[0]; g_psq[b * 64 + blk] = sg[0]; }
}

// ---------------- kernel 2: finalize mean / rsigma ----------------
__global__ void k_reduce2() {
    int tid = threadIdx.x;
    int b = tid / 64, j = tid % 64;
    __shared__ float ss[256], sg[256];
    ss[tid] = g_psum[tid]; sg[tid] = g_psq[tid];
    __syncthreads();
    for (int off = 32; off >= 1; off >>= 1) {
        if (j < off) { ss[tid] += ss[tid + off]; sg[tid] += sg[tid + off]; }
        __syncthreads();
    }
    if (j == 0) {
        float mu = ss[tid] * (1.f / (float)NPB);
        float var = sg[tid] * (1.f / (float)NPB) - mu * mu;
        g_mu[b] = mu;
        g_rs[b] = rsqrtf(var + 1e-5f);
    }
}

// ---------------- kernel 3: normalize + QKV GEMM ----------------
__global__ void __launch_bounds__(256) k_qkv(const float* __restrict__ x,
                                             const float* __restrict__ gamma,
                                             const float* __restrict__ beta) {
    int b  = blockIdx.z;
    int i0 = blockIdx.x * 64;
    int o0 = blockIdx.y * 64;
    float mu = g_mu[b], rs = g_rs[b];
    __shared__ float xs[16][68];
    __shared__ float ws[16][68];
    int tid = threadIdx.x;
    int tx = tid & 15, ty = tid >> 4;
    int lrow = tid >> 4, lcol = (tid & 15) * 4;
    const float* xb = x + (size_t)b * NPB;
    float acc[4][4] = {};
    for (int k0 = 0; k0 < CDIM; k0 += 16) {
        int c = k0 + lrow;
        float a = rs * gamma[c];
        float bb = beta[c] - mu * a;
        float4 xv = *(const float4*)(xb + (size_t)c * NTOK + i0 + lcol);
        xs[lrow][lcol + 0] = xv.x * a + bb;
        xs[lrow][lcol + 1] = xv.y * a + bb;
        xs[lrow][lcol + 2] = xv.z * a + bb;
        xs[lrow][lcol + 3] = xv.w * a + bb;
        float4 wv = *(const float4*)(g_wt_qkv + c * OQKV + o0 + lcol);
        ws[lrow][lcol + 0] = wv.x;
        ws[lrow][lcol + 1] = wv.y;
        ws[lrow][lcol + 2] = wv.z;
        ws[lrow][lcol + 3] = wv.w;
        __syncthreads();
        #pragma unroll
        for (int kk = 0; kk < 16; kk++) {
            float av[4], bv[4];
            #pragma unroll
            for (int u = 0; u < 4; u++) av[u] = xs[kk][tx * 4 + u];
            #pragma unroll
            for (int u = 0; u < 4; u++) bv[u] = ws[kk][ty * 4 + u];
            #pragma unroll
            for (int oi = 0; oi < 4; oi++)
                #pragma unroll
                for (int ii = 0; ii < 4; ii++)
                    acc[oi][ii] = fmaf(bv[oi], av[ii], acc[oi][ii]);
        }
        __syncthreads();
    }
    #pragma unroll
    for (int oi = 0; oi < 4; oi++) {
        int o = o0 + ty * 4 + oi;
        int which = o >> 7;
        int head = (o & 127) >> 5;
        int d = o & 31;
        int bh = b * HEADS + head;
        #pragma unroll
        for (int ii = 0; ii < 4; ii++) {
            int i = i0 + tx * 4 + ii;
            float val = acc[oi][ii];
            size_t idx = ((size_t)bh * NTOK + i) * DH + d;
            if (which == 0)
                g_qf[idx] = tf32r(val * SCALE_LOG2E);
            else if (which == 1)
                g_kf[idx] = tf32r(val);
            else
                g_vb[idx] = __float2bfloat16_rn(val);
        }
    }
}

// ---------------- kernel 4: flash attention (tf32 QK, bf16 PV) -------------
// grid: (32 q-tiles, 16 bh), 128 threads / 4 warps. 128 q rows/CTA, 64-key tiles.
__global__ void __launch_bounds__(128) k_attn_mma() {
    __shared__ __align__(16) float Qs[128][36];
    __shared__ __align__(16) float Ks[2][64][36];
    __shared__ __align__(16) __nv_bfloat16 Vs[2][64][40];

    int tid = threadIdx.x;
    int wid = tid >> 5, lane = tid & 31;
    int bh = blockIdx.y;
    int i0 = blockIdx.x * 128;
    int wrow = wid * 32;

    const float* kb = g_kf + (size_t)bh * NTOK * DH;
    const __nv_bfloat16* vb = g_vb + (size_t)bh * NTOK * DH;
    const float* qg = g_qf + (size_t)bh * NTOK * DH;

    // load Q tile (128 x 32 fp32): one row per thread
    {
        const uint4* qp = (const uint4*)(qg + (size_t)(i0 + tid) * DH);
        #pragma unroll
        for (int c = 0; c < 8; c++)
            *(uint4*)&Qs[tid][c * 4] = qp[c];
    }
    __syncthreads();

    int lr4 = lane >> 2, lc = lane & 3;
    int lr = lane & 7, lm = lane >> 3;          // for ldmatrix (V only)

    // Q fragments: tf32 A m16k8, per (mt, ks): a0..a3
    uint32_t qf[2][4][4];
    #pragma unroll
    for (int mt = 0; mt < 2; mt++)
        #pragma unroll
        for (int ks = 0; ks < 4; ks++) {
            int r0 = wrow + mt * 16 + lr4;
            qf[mt][ks][0] = __float_as_uint(Qs[r0    ][ks * 8 + lc]);
            qf[mt][ks][1] = __float_as_uint(Qs[r0 + 8][ks * 8 + lc]);
            qf[mt][ks][2] = __float_as_uint(Qs[r0    ][ks * 8 + 4 + lc]);
            qf[mt][ks][3] = __float_as_uint(Qs[r0 + 8][ks * 8 + 4 + lc]);
        }

    float o[2][4][4] = {};
    float mrow[4] = {-CUDART_INF_F, -CUDART_INF_F, -CUDART_INF_F, -CUDART_INF_F};
    float lrow[4] = {};

    // prefetch addressing
    int krow = tid >> 1, kc0 = (tid & 1) * 16;            // K: 64 rows x 32 floats
    int vr0 = tid >> 2, vc0 = (tid & 3) * 8, vr1 = 32 + vr0; // V: 64 rows x 32 bf16

    uint4 kp[4], vp0, vp1;
    #pragma unroll
    for (int j = 0; j < 4; j++)
        kp[j] = *(const uint4*)(kb + (size_t)krow * DH + kc0 + j * 4);
    vp0 = *(const uint4*)(vb + (size_t)vr0 * DH + vc0);
    vp1 = *(const uint4*)(vb + (size_t)vr1 * DH + vc0);
    #pragma unroll
    for (int j = 0; j < 4; j++)
        *(uint4*)&Ks[0][krow][kc0 + j * 4] = kp[j];
    *(uint4*)&Vs[0][vr0][vc0] = vp0;
    *(uint4*)&Vs[0][vr1][vc0] = vp1;
    __syncthreads();

    for (int t = 0; t < NTOK / 64; t++) {
        int buf = t & 1;
        if (t < NTOK / 64 - 1) {
            size_t j0 = (size_t)(t + 1) * 64;
            #pragma unroll
            for (int j = 0; j < 4; j++)
                kp[j] = *(const uint4*)(kb + (j0 + krow) * DH + kc0 + j * 4);
            vp0 = *(const uint4*)(vb + (j0 + vr0) * DH + vc0);
            vp1 = *(const uint4*)(vb + (j0 + vr1) * DH + vc0);
        }

        // ---- S = Q @ K^T : per warp 32 x 64 (tf32) ----
        float s[2][8][4] = {};
        #pragma unroll
        for (int nt = 0; nt < 8; nt++) {
            int kr = nt * 8 + lr4;
            #pragma unroll
            for (int ks = 0; ks < 4; ks++) {
                uint32_t b0 = __float_as_uint(Ks[buf][kr][ks * 8 + lc]);
                uint32_t b1 = __float_as_uint(Ks[buf][kr][ks * 8 + 4 + lc]);
                MMA_TF32(s[0][nt], qf[0][ks], b0, b1);
                MMA_TF32(s[1][nt], qf[1][ks], b0, b1);
            }
        }

        // ---- online softmax (log2 domain) ----
        #pragma unroll
        for (int mt = 0; mt < 2; mt++)
            #pragma unroll
            for (int h = 0; h < 2; h++) {
                int sl = mt * 2 + h;
                float mx = mrow[sl];
                #pragma unroll
                for (int nt = 0; nt < 8; nt++)
                    mx = fmaxf(mx, fmaxf(s[mt][nt][h * 2], s[mt][nt][h * 2 + 1]));
                mx = fmaxf(mx, __shfl_xor_sync(0xffffffffu, mx, 1));
                mx = fmaxf(mx, __shfl_xor_sync(0xffffffffu, mx, 2));
                float sc = ex2(mrow[sl] - mx);
                mrow[sl] = mx;
                float ls = 0.f;
                #pragma unroll
                for (int nt = 0; nt < 8; nt++) {
                    float p0 = ex2(s[mt][nt][h * 2]     - mx);
                    float p1 = ex2(s[mt][nt][h * 2 + 1] - mx);
                    s[mt][nt][h * 2]     = p0;
                    s[mt][nt][h * 2 + 1] = p1;
                    ls += p0 + p1;
                }
                lrow[sl] = lrow[sl] * sc + ls;
                #pragma unroll
                for (int ntd = 0; ntd < 4; ntd++) {
                    o[mt][ntd][h * 2]     *= sc;
                    o[mt][ntd][h * 2 + 1] *= sc;
                }
            }

        // pack probs into bf16 A fragments (m16k16 per 16-key chunk)
        uint32_t af[2][4][4];
        #pragma unroll
        for (int mt = 0; mt < 2; mt++)
            #pragma unroll
            for (int kk = 0; kk < 4; kk++) {
                PACK_BF16X2(af[mt][kk][0], s[mt][2 * kk][0],     s[mt][2 * kk][1]);
                PACK_BF16X2(af[mt][kk][1], s[mt][2 * kk][2],     s[mt][2 * kk][3]);
                PACK_BF16X2(af[mt][kk][2], s[mt][2 * kk + 1][0], s[mt][2 * kk + 1][1]);
                PACK_BF16X2(af[mt][kk][3], s[mt][2 * kk + 1][2], s[mt][2 * kk + 1][3]);
            }

        // ---- O += P @ V (bf16) ----
        #pragma unroll
        for (int kk = 0; kk < 4; kk++) {
            uint32_t vf[2][4];
            #pragma unroll
            for (int dp = 0; dp < 2; dp++)
                ldsm_x4_t(vf[dp],
                          smem_u32(&Vs[buf][kk * 16 + (lm & 1) * 8 + lr][dp * 16 + (lm >> 1) * 8]));
            #pragma unroll
            for (int mt = 0; mt < 2; mt++) {
                MMA_BF16(o[mt][0], af[mt][kk], vf[0][0], vf[0][1]);
                MMA_BF16(o[mt][1], af[mt][kk], vf[0][2], vf[0][3]);
                MMA_BF16(o[mt][2], af[mt][kk], vf[1][0], vf[1][1]);
                MMA_BF16(o[mt][3], af[mt][kk], vf[1][2], vf[1][3]);
            }
        }

        if (t < NTOK / 64 - 1) {
            #pragma unroll
            for (int j = 0; j < 4; j++)
                *(uint4*)&Ks[buf ^ 1][krow][kc0 + j * 4] = kp[j];
            *(uint4*)&Vs[buf ^ 1][vr0][vc0] = vp0;
            *(uint4*)&Vs[buf ^ 1][vr1][vc0] = vp1;
        }
        __syncthreads();
    }

    // ---- epilogue ----
    float linv[4];
    #pragma unroll
    for (int sl = 0; sl < 4; sl++) {
        float v = lrow[sl];
        v += __shfl_xor_sync(0xffffffffu, v, 1);
        v += __shfl_xor_sync(0xffffffffu, v, 2);
        linv[sl] = 1.f / v;
    }
    int b = bh >> 2, hd = bh & 3;
    float* dst = g_ao + ((size_t)b * HID + hd * DH) * NTOK;
    int rbase = i0 + wrow + (lane >> 2);
    int cbase = (lane & 3) * 2;
    #pragma unroll
    for (int mt = 0; mt < 2; mt++)
        #pragma unroll
        for (int h = 0; h < 2; h++) {
            int i = rbase + mt * 16 + h * 8;
            float inv = linv[mt * 2 + h];
            #pragma unroll
            for (int ntd = 0; ntd < 4; ntd++) {
                int d = ntd * 8 + cbase;
                dst[(size_t)d * NTOK + i]       = o[mt][ntd][h * 2]     * inv;
                dst[(size_t)(d + 1) * NTOK + i] = o[mt][ntd][h * 2 + 1] * inv;
            }
        }
}

// ---------------- kernel 5: output GEMM + bias ----------------
__global__ void __launch_bounds__(256) k_out(float* __restrict__ y,
                                             const float* __restrict__ b_out) {
    int b  = blockIdx.z;
    int i0 = blockIdx.x * 64;
    int o0 = blockIdx.y * 64;
    __shared__ float xs[16][68];
    __shared__ float ws[16][68];
    int tid = threadIdx.x;
    int tx = tid & 15, ty = tid >> 4;
    int lrow = tid >> 4, lcol = (tid & 15) * 4;
    const float* abuf = g_ao + (size_t)b * HID * NTOK;
    float acc[4][4] = {};
    for (int k0 = 0; k0 < HID; k0 += 16) {
        int c = k0 + lrow;
        float4 xv = *(const float4*)(abuf + (size_t)c * NTOK + i0 + lcol);
        xs[lrow][lcol + 0] = xv.x;
        xs[lrow][lcol + 1] = xv.y;
        xs[lrow][lcol + 2] = xv.z;
        xs[lrow][lcol + 3] = xv.w;
        float4 wv = *(const float4*)(g_wt_out + c * CDIM + o0 + lcol);
        ws[lrow][lcol + 0] = wv.x;
        ws[lrow][lcol + 1] = wv.y;
        ws[lrow][lcol + 2] = wv.z;
        ws[lrow][lcol + 3] = wv.w;
        __syncthreads();
        #pragma unroll
        for (int kk = 0; kk < 16; kk++) {
            float av[4], bv[4];
            #pragma unroll
            for (int u = 0; u < 4; u++) av[u] = xs[kk][tx * 4 + u];
            #pragma unroll
            for (int u = 0; u < 4; u++) bv[u] = ws[kk][ty * 4 + u];
            #pragma unroll
            for (int oi = 0; oi < 4; oi++)
                #pragma unroll
                for (int ii = 0; ii < 4; ii++)
                    acc[oi][ii] = fmaf(bv[oi], av[ii], acc[oi][ii]);
        }
        __syncthreads();
    }
    #pragma unroll
    for (int oi = 0; oi < 4; oi++) {
        int o = o0 + ty * 4 + oi;
        float bias = b_out[o];
        #pragma unroll
        for (int ii = 0; ii < 4; ii++) {
            int i = i0 + tx * 4 + ii;
            y[((size_t)b * CDIM + o) * NTOK + i] = acc[oi][ii] + bias;
        }
    }
}

// ---------------- launch ----------------
extern "C" void kernel_launch(void* const* d_in, const int* in_sizes, int n_in,
                              void* d_out, int out_size) {
    const float* x     = (const float*)d_in[0];
    const float* gamma = (const float*)d_in[1];
    const float* beta  = (const float*)d_in[2];
    const float* w_qkv = (const float*)d_in[3];
    const float* w_out = (const float*)d_in[4];
    const float* b_out = (const float*)d_in[5];
    float* y = (float*)d_out;

    k_transpose<<<384, 256>>>(w_qkv, w_out);
    k_reduce1<<<dim3(64, BATCH), 256>>>(x);
    k_reduce2<<<1, 256>>>();
    k_qkv<<<dim3(NTOK / 64, OQKV / 64, BATCH), 256>>>(x, gamma, beta);
    k_attn_mma<<<dim3(NTOK / 128, BATCH * HEADS), 128>>>();
    k_out<<<dim3(NTOK / 64, CDIM / 64, BATCH), 256>>>(y, b_out);
}